// round 6
// baseline (speedup 1.0000x reference)
#include <cuda_runtime.h>

// Fused sparse-UNet backbone, round 6.
// Crossbar fix: broadcast LDS costs full register-writeback wavefronts, so
// weights are now distributed via shfl.idx (shuffle network, zero crossbar
// cost): each lane loads COUT/32 lane-distinct weight floats (one conflict-
// free LDS), then CC shuffles hand every lane its columns. Activations are
// loaded per row-group (lane-grouped, 1-2 LDS.128). Per warp-k at COUT=128:
// 12 wavefronts vs 32 FFMA2 -> FMA-bound.

#define THREADS 256
#define RROWS   128
#define PITCH   132          // floats; 132*4=528 B, 16B-aligned rows
#define WBUF    8192         // weight staging buffer, floats (32 KB)

typedef unsigned long long ull;

__device__ __forceinline__ ull fma2(ull a, ull b, ull c) {
    ull d;
    asm("fma.rn.f32x2 %0, %1, %2, %3;" : "=l"(d) : "l"(a), "l"(b), "l"(c));
    return d;
}
__device__ __forceinline__ ull dup2(float x) {
    ull r;
    asm("mov.b64 %0, {%1, %1};" : "=l"(r) : "f"(x));
    return r;
}
__device__ __forceinline__ float2 unpk2(ull v) {
    float2 r;
    asm("mov.b64 {%0, %1}, %2;" : "=f"(r.x), "=f"(r.y) : "l"(v));
    return r;
}
__device__ __forceinline__ ull pk2(float2 v) {
    ull r;
    asm("mov.b64 %0, {%1, %2};" : "=l"(r) : "f"(v.x), "f"(v.y));
    return r;
}
__device__ __forceinline__ float frelu(float v) { return v > 0.f ? v : 0.f; }

// Thread (rg, cg): rows [rg*TR, rg*TR+TR), cols [cg*CC, cg*CC+CC).
//   rgroups = RROWS/TR, cgroups = COUT/CC, rgroups*cgroups == THREADS.
// Weights: lane loads WL = COUT/32 floats lane-distinct, shfl.idx distributes.
// EPI: 0 relu->smem ; 1 relu+pairsum(redSrc)->smem ; 2 relu->gmem [N,COUT]
template<int CIN, int COUT, int TR, int CC, int EPI>
__device__ __forceinline__ void mm3(const float* __restrict__ sSrc,
                                    const float* __restrict__ Wg,
                                    float* __restrict__ sW,
                                    float* __restrict__ dst,
                                    const float* __restrict__ redSrc,
                                    float* __restrict__ gout,
                                    int row0, int Ntot, int tid)
{
    constexpr int CG    = COUT / CC;                 // col groups
    constexpr int WL    = COUT / 32;                 // weight floats per lane
    constexpr int PAIRS = TR / 2;
    static_assert((RROWS / TR) * CG == THREADS, "tiling");
    static_assert(CC % WL == 0, "shfl mapping");

    constexpr int KCC = (WBUF / COUT < CIN) ? (WBUF / COUT) : CIN;
    constexpr int NCH = CIN / KCC;

    const int lane = tid & 31;
    const int cg   = tid % CG;
    const int rg   = tid / CG;
    const int rbase = rg * TR;

    ull acc[PAIRS][CC];
#pragma unroll
    for (int p = 0; p < PAIRS; p++)
#pragma unroll
        for (int j = 0; j < CC; j++) acc[p][j] = 0ull;

    for (int ch = 0; ch < NCH; ch++) {
        __syncthreads();                              // sW free / prev stores visible
        {
            const float4* ws = (const float4*)(Wg + (size_t)ch * KCC * COUT);
            float4* wd = (float4*)sW;
            constexpr int WN = KCC * COUT / 4;
            for (int i = tid; i < WN; i += THREADS) wd[i] = ws[i];
        }
        __syncthreads();

        const float* sp = sSrc + (size_t)ch * KCC * PITCH + rbase;
#pragma unroll 2
        for (int k = 0; k < KCC; k++) {
            // activations: TR rows for this row-group (lane-grouped LDS.128)
            ull A[PAIRS];
            if constexpr (TR == 8) {
                ulonglong2 a0 = *(const ulonglong2*)(sp + k * PITCH);
                ulonglong2 a1 = *(const ulonglong2*)(sp + k * PITCH + 4);
                A[0] = a0.x; A[1] = a0.y; A[2] = a1.x; A[3] = a1.y;
            } else { // TR == 4
                ulonglong2 a0 = *(const ulonglong2*)(sp + k * PITCH);
                A[0] = a0.x; A[1] = a0.y;
            }

            // weights: lane-distinct chunk, then shfl.idx distribution
            float wl[WL];
            {
                const float* wp = sW + k * COUT + WL * lane;
                if constexpr (WL == 4) {
                    float4 t = *(const float4*)wp;
                    wl[0] = t.x; wl[1] = t.y; wl[2] = t.z; wl[3] = t.w;
                } else if constexpr (WL == 2) {
                    float2 t = *(const float2*)wp;
                    wl[0] = t.x; wl[1] = t.y;
                } else {
                    wl[0] = *wp;
                }
            }
#pragma unroll
            for (int j = 0; j < CC; j++) {
                const int src = cg * (CC / WL) + j / WL;
                float wv = __shfl_sync(0xffffffffu, wl[j % WL], src);
                ull wj = dup2(wv);
#pragma unroll
                for (int p = 0; p < PAIRS; p++)
                    acc[p][j] = fma2(A[p], wj, acc[p][j]);   // A*w + acc
            }
        }
    }

    // finalize in registers (redSrc reads happen BEFORE the sync)
#pragma unroll
    for (int j = 0; j < CC; j++) {
        const int c = cg * CC + j;
#pragma unroll
        for (int p = 0; p < PAIRS; p++) {
            float2 v = unpk2(acc[p][j]);
            v.x = frelu(v.x); v.y = frelu(v.y);
            if (EPI == 1) {
                const int r0 = rbase + 2 * p;
                const float2 ra = *(const float2*)&redSrc[(2 * c) * PITCH + r0];
                const float2 rb = *(const float2*)&redSrc[(2 * c + 1) * PITCH + r0];
                v.x += ra.x + rb.x;
                v.y += ra.y + rb.y;
            }
            acc[p][j] = pk2(v);
        }
    }

    if (EPI == 2) {
#pragma unroll
        for (int j = 0; j < CC; j++) {
            const int c = cg * CC + j;
#pragma unroll
            for (int p = 0; p < PAIRS; p++) {
                float2 v = unpk2(acc[p][j]);
                const int g0 = row0 + rbase + 2 * p;
                if (g0 < Ntot)     gout[(size_t)g0 * COUT + c]       = v.x;
                if (g0 + 1 < Ntot) gout[(size_t)(g0 + 1) * COUT + c] = v.y;
            }
        }
        return;
    }

    __syncthreads();                                  // all reads of src done
#pragma unroll
    for (int j = 0; j < CC; j++) {
        const int c = cg * CC + j;
#pragma unroll
        for (int p = 0; p < PAIRS; p++)
            *(float2*)&dst[c * PITCH + rbase + 2 * p] = unpk2(acc[p][j]);
    }
}

// smem: sE1 32ch, sE2 64ch, sC 256ch (PITCH floats/ch) + sW
#define SMEM_FLOATS ((32 + 64 + 256) * PITCH + WBUF)
#define SMEM_BYTES  (SMEM_FLOATS * 4)

__global__ void __launch_bounds__(THREADS, 1)
fused_backbone_kernel(const float* __restrict__ feat,
                      const float* __restrict__ Win,
                      const float* __restrict__ We1, const float* __restrict__ We2,
                      const float* __restrict__ We3,
                      const float* __restrict__ Wl1, const float* __restrict__ Wl2,
                      const float* __restrict__ Wl3,
                      const float* __restrict__ Wm1, const float* __restrict__ Wm2,
                      const float* __restrict__ Wm3,
                      const float* __restrict__ Wu1, const float* __restrict__ Wu2,
                      const float* __restrict__ Wu3,
                      float* __restrict__ out, int Ntot)
{
    extern __shared__ float smem[];
    float* sE1 = smem;                        // e1: 32 ch (persists)
    float* sE2 = sE1 + 32 * PITCH;            // e2: 64 ch (persists)
    float* sC  = sE2 + 64 * PITCH;            // workspace: 256 ch
    float* sW  = sC + 256 * PITCH;            // weight chunk buffer

    const int tid  = threadIdx.x;
    const int row0 = blockIdx.x * RROWS;

    // feat[row0 : row0+128, 0:16] -> sC[0:16] channel-major (coalesced reads)
    for (int idx = tid; idx < 16 * RROWS; idx += THREADS) {
        const int c = idx & 15, r = idx >> 4;
        const int gr = row0 + r;
        sC[c * PITCH + r] = (gr < Ntot) ? feat[(size_t)gr * 16 + c] : 0.f;
    }
    // mm3's leading __syncthreads covers the store->read hazard

    // tilings: COUT=128 -> TR 8, CC 8 ; COUT=64 -> TR 4, CC 8 ; COUT=32 -> TR 4, CC 4
    // encoder (src/dst may alias: epilogues are reg-deferred)
    mm3<16, 32, 4, 4, 0>(sC, Win, sW, sC, nullptr, nullptr, 0, 0, tid);    // x   -> sC[0:32]
    mm3<32, 32, 4, 4, 0>(sC, We1, sW, sE1, nullptr, nullptr, 0, 0, tid);   // e1  -> sE1
    mm3<32, 64, 4, 8, 0>(sE1, We2, sW, sE2, nullptr, nullptr, 0, 0, tid);  // e2  -> sE2
    mm3<64, 128, 8, 8, 0>(sE2, We3, sW, sC, nullptr, nullptr, 0, 0, tid);  // e3  -> sC[0:128]

    // decoder stage 3 (C=128): cat3 = [e3 | lat3] = sC[0:256]
    mm3<128, 128, 8, 8, 0>(sC, Wl3, sW, sC + 128 * PITCH, nullptr, nullptr, 0, 0, tid); // lat3
    mm3<256, 128, 8, 8, 1>(sC, Wm3, sW, sC, sC, nullptr, 0, 0, tid);       // t3 -> sC[0:128]
    mm3<128, 64, 4, 8, 0>(sC, Wu3, sW, sC, nullptr, nullptr, 0, 0, tid);   // x2 -> sC[0:64]

    // decoder stage 2 (C=64): cat2 = [x2 | lat2] = sC[0:128]
    mm3<64, 64, 4, 8, 0>(sE2, Wl2, sW, sC + 64 * PITCH, nullptr, nullptr, 0, 0, tid);   // lat2
    mm3<128, 64, 4, 8, 1>(sC, Wm2, sW, sC, sC, nullptr, 0, 0, tid);        // t2 -> sC[0:64]
    mm3<64, 32, 4, 4, 0>(sC, Wu2, sW, sC, nullptr, nullptr, 0, 0, tid);    // x1 -> sC[0:32]

    // decoder stage 1 (C=32): cat1 = [x1 | lat1] = sC[0:64]
    mm3<32, 32, 4, 4, 0>(sE1, Wl1, sW, sC + 32 * PITCH, nullptr, nullptr, 0, 0, tid);   // lat1
    mm3<64, 32, 4, 4, 1>(sC, Wm1, sW, sC, sC, nullptr, 0, 0, tid);         // t1 -> sC[0:32]

    // final upsample -> gmem [N, 32]
    mm3<32, 32, 4, 4, 2>(sC, Wu1, sW, nullptr, nullptr, out, row0, Ntot, tid);
}

extern "C" void kernel_launch(void* const* d_in, const int* in_sizes, int n_in,
                              void* d_out, int out_size)
{
    const float* feat = (const float*)d_in[0];
    // d_in[1] = coords (int32) — sparse structure only; unused for 1x1 subm convs
    const float* Win = (const float*)d_in[2];
    const float* We1 = (const float*)d_in[3];
    const float* We2 = (const float*)d_in[4];
    const float* We3 = (const float*)d_in[5];
    const float* Wl1 = (const float*)d_in[6];
    const float* Wl2 = (const float*)d_in[7];
    const float* Wl3 = (const float*)d_in[8];
    const float* Wm1 = (const float*)d_in[9];
    const float* Wm2 = (const float*)d_in[10];
    const float* Wm3 = (const float*)d_in[11];
    const float* Wu1 = (const float*)d_in[12];
    const float* Wu2 = (const float*)d_in[13];
    const float* Wu3 = (const float*)d_in[14];

    const int N = in_sizes[0] / 16;

    cudaFuncSetAttribute(fused_backbone_kernel,
                         cudaFuncAttributeMaxDynamicSharedMemorySize, SMEM_BYTES);

    const int grid = (N + RROWS - 1) / RROWS;
    fused_backbone_kernel<<<grid, THREADS, SMEM_BYTES>>>(
        feat, Win, We1, We2, We3, Wl1, Wl2, Wl3,
        Wm1, Wm2, Wm3, Wu1, Wu2, Wu3, (float*)d_out, N);
}

// round 7
// speedup vs baseline: 1.2115x; 1.2115x over previous
#include <cuda_runtime.h>

// Fused sparse-UNet backbone, round 7.
// Balanced outer-product tiling: crossbar traffic per k is 4*(R*CT + C*RT) B
// (LDS writeback is 512B/instr/warp even for broadcasts). Minimizing with
// RT*CT=256 threads: COUT=128 -> 8 rows x 8 cols per thread (16 wf vs 32
// FFMA2 per warp-k, crossbar == fma). Shuffle distribution (R6) reverted:
// SHFL rides the LSU path and costs like LDS.

#define THREADS 256
#define RROWS   128
#define PITCH   132          // floats; 132*4=528 B, 16B-aligned rows
#define WBUF    8192         // weight staging buffer, floats (32 KB)

typedef unsigned long long ull;

__device__ __forceinline__ ull fma2(ull a, ull b, ull c) {
    ull d;
    asm("fma.rn.f32x2 %0, %1, %2, %3;" : "=l"(d) : "l"(a), "l"(b), "l"(c));
    return d;
}
__device__ __forceinline__ ull dup2(float x) {
    ull r;
    asm("mov.b64 %0, {%1, %1};" : "=l"(r) : "f"(x));
    return r;
}
__device__ __forceinline__ float2 unpk2(ull v) {
    float2 r;
    asm("mov.b64 {%0, %1}, %2;" : "=f"(r.x), "=f"(r.y) : "l"(v));
    return r;
}
__device__ __forceinline__ ull pk2(float2 v) {
    ull r;
    asm("mov.b64 %0, {%1, %2};" : "=l"(r) : "f"(v.x), "f"(v.y));
    return r;
}
__device__ __forceinline__ float frelu(float v) { return v > 0.f ? v : 0.f; }

// Thread grid: CG = COUT/CCG col-groups, RG = THREADS/CG row-groups.
// Thread: cg = tid % CG (cols [cg*CCG, +CCG)), rg = tid / CG (rows [rg*TRG, +TRG)).
// EPI: 0 relu->smem ; 1 relu+pairsum(redSrc)->smem ; 2 relu->gmem [N,COUT]
template<int CIN, int COUT, int TRG, int CCG, int EPI>
__device__ __forceinline__ void mm4(const float* __restrict__ sSrc,
                                    const float* __restrict__ Wg,
                                    float* __restrict__ sW,
                                    float* __restrict__ dst,
                                    const float* __restrict__ redSrc,
                                    float* __restrict__ gout,
                                    int row0, int Ntot, int tid)
{
    constexpr int CG    = COUT / CCG;
    constexpr int RG    = THREADS / CG;
    constexpr int PAIRS = TRG / 2;
    static_assert(RG * TRG == RROWS, "row tiling");
    static_assert(TRG == 4 || TRG == 8, "TRG");
    static_assert(CCG == 4 || CCG == 8, "CCG");

    constexpr int KCC = (WBUF / COUT < CIN) ? (WBUF / COUT) : CIN;
    constexpr int NCH = CIN / KCC;

    const int cg    = tid % CG;
    const int rg    = tid / CG;
    const int rbase = rg * TRG;
    const int cbase = cg * CCG;

    ull acc[PAIRS][CCG];
#pragma unroll
    for (int p = 0; p < PAIRS; p++)
#pragma unroll
        for (int j = 0; j < CCG; j++) acc[p][j] = 0ull;

    for (int ch = 0; ch < NCH; ch++) {
        __syncthreads();                              // sW free / prev stores visible
        {
            const float4* ws = (const float4*)(Wg + (size_t)ch * KCC * COUT);
            float4* wd = (float4*)sW;
            constexpr int WN = KCC * COUT / 4;
            for (int i = tid; i < WN; i += THREADS) wd[i] = ws[i];
        }
        __syncthreads();

        const float* sp = sSrc + (size_t)ch * KCC * PITCH + rbase;
#pragma unroll 2
        for (int k = 0; k < KCC; k++) {
            ull A[PAIRS];
            if constexpr (TRG == 8) {
                ulonglong2 a0 = *(const ulonglong2*)(sp + k * PITCH);
                ulonglong2 a1 = *(const ulonglong2*)(sp + k * PITCH + 4);
                A[0] = a0.x; A[1] = a0.y; A[2] = a1.x; A[3] = a1.y;
            } else {
                ulonglong2 a0 = *(const ulonglong2*)(sp + k * PITCH);
                A[0] = a0.x; A[1] = a0.y;
            }

            const float* wp = sW + k * COUT + cbase;
            float w[CCG];
            if constexpr (CCG == 8) {
                float4 t0 = *(const float4*)wp;
                float4 t1 = *(const float4*)(wp + 4);
                w[0] = t0.x; w[1] = t0.y; w[2] = t0.z; w[3] = t0.w;
                w[4] = t1.x; w[5] = t1.y; w[6] = t1.z; w[7] = t1.w;
            } else {
                float4 t0 = *(const float4*)wp;
                w[0] = t0.x; w[1] = t0.y; w[2] = t0.z; w[3] = t0.w;
            }
#pragma unroll
            for (int j = 0; j < CCG; j++) {
                ull wj = dup2(w[j]);
#pragma unroll
                for (int p = 0; p < PAIRS; p++)
                    acc[p][j] = fma2(A[p], wj, acc[p][j]);   // A*w + acc
            }
        }
    }

    // finalize in registers (redSrc reads BEFORE the sync)
#pragma unroll
    for (int j = 0; j < CCG; j++) {
        const int c = cbase + j;
#pragma unroll
        for (int p = 0; p < PAIRS; p++) {
            float2 v = unpk2(acc[p][j]);
            v.x = frelu(v.x); v.y = frelu(v.y);
            if (EPI == 1) {
                const int r0 = rbase + 2 * p;
                const float2 ra = *(const float2*)&redSrc[(2 * c) * PITCH + r0];
                const float2 rb = *(const float2*)&redSrc[(2 * c + 1) * PITCH + r0];
                v.x += ra.x + rb.x;
                v.y += ra.y + rb.y;
            }
            acc[p][j] = pk2(v);
        }
    }

    if (EPI == 2) {
        // final stage (CCG==4): row-major float4 stores to gmem
#pragma unroll
        for (int rr = 0; rr < TRG; rr++) {
            const int g = row0 + rbase + rr;
            if (g < Ntot) {
                float4 o;
                float2 v0 = unpk2(acc[rr / 2][0]);
                float2 v1 = unpk2(acc[rr / 2][1]);
                float2 v2 = unpk2(acc[rr / 2][2]);
                float2 v3 = unpk2(acc[rr / 2][3]);
                if (rr & 1) { o.x = v0.y; o.y = v1.y; o.z = v2.y; o.w = v3.y; }
                else        { o.x = v0.x; o.y = v1.x; o.z = v2.x; o.w = v3.x; }
                *(float4*)&gout[(size_t)g * COUT + cbase] = o;
            }
        }
        return;
    }

    __syncthreads();                                  // all reads of src done
#pragma unroll
    for (int j = 0; j < CCG; j++) {
        const int c = cbase + j;
#pragma unroll
        for (int p = 0; p < PAIRS; p++)
            *(float2*)&dst[c * PITCH + rbase + 2 * p] = unpk2(acc[p][j]);
    }
}

// smem: sE1 32ch, sE2 64ch, sC 256ch (PITCH floats/ch) + sW
#define SMEM_FLOATS ((32 + 64 + 256) * PITCH + WBUF)
#define SMEM_BYTES  (SMEM_FLOATS * 4)

__global__ void __launch_bounds__(THREADS, 1)
fused_backbone_kernel(const float* __restrict__ feat,
                      const float* __restrict__ Win,
                      const float* __restrict__ We1, const float* __restrict__ We2,
                      const float* __restrict__ We3,
                      const float* __restrict__ Wl1, const float* __restrict__ Wl2,
                      const float* __restrict__ Wl3,
                      const float* __restrict__ Wm1, const float* __restrict__ Wm2,
                      const float* __restrict__ Wm3,
                      const float* __restrict__ Wu1, const float* __restrict__ Wu2,
                      const float* __restrict__ Wu3,
                      float* __restrict__ out, int Ntot)
{
    extern __shared__ float smem[];
    float* sE1 = smem;                        // e1: 32 ch (persists)
    float* sE2 = sE1 + 32 * PITCH;            // e2: 64 ch (persists)
    float* sC  = sE2 + 64 * PITCH;            // workspace: 256 ch
    float* sW  = sC + 256 * PITCH;            // weight chunk buffer

    const int tid  = threadIdx.x;
    const int row0 = blockIdx.x * RROWS;

    // feat[row0 : row0+128, 0:16] -> sC[0:16] channel-major (coalesced reads)
    for (int idx = tid; idx < 16 * RROWS; idx += THREADS) {
        const int c = idx & 15, r = idx >> 4;
        const int gr = row0 + r;
        sC[c * PITCH + r] = (gr < Ntot) ? feat[(size_t)gr * 16 + c] : 0.f;
    }
    // mm4's leading __syncthreads covers the store->read hazard

    // encoder (src/dst may alias: epilogues are reg-deferred)
    mm4<16, 32, 4, 4, 0>(sC, Win, sW, sC, nullptr, nullptr, 0, 0, tid);    // x   -> sC[0:32]
    mm4<32, 32, 4, 4, 0>(sC, We1, sW, sE1, nullptr, nullptr, 0, 0, tid);   // e1  -> sE1
    mm4<32, 64, 8, 4, 0>(sE1, We2, sW, sE2, nullptr, nullptr, 0, 0, tid);  // e2  -> sE2
    mm4<64, 128, 8, 8, 0>(sE2, We3, sW, sC, nullptr, nullptr, 0, 0, tid);  // e3  -> sC[0:128]

    // decoder stage 3 (C=128): cat3 = [e3 | lat3] = sC[0:256]
    mm4<128, 128, 8, 8, 0>(sC, Wl3, sW, sC + 128 * PITCH, nullptr, nullptr, 0, 0, tid); // lat3
    mm4<256, 128, 8, 8, 1>(sC, Wm3, sW, sC, sC, nullptr, 0, 0, tid);       // t3 -> sC[0:128]
    mm4<128, 64, 8, 4, 0>(sC, Wu3, sW, sC, nullptr, nullptr, 0, 0, tid);   // x2 -> sC[0:64]

    // decoder stage 2 (C=64): cat2 = [x2 | lat2] = sC[0:128]
    mm4<64, 64, 8, 4, 0>(sE2, Wl2, sW, sC + 64 * PITCH, nullptr, nullptr, 0, 0, tid);   // lat2
    mm4<128, 64, 8, 4, 1>(sC, Wm2, sW, sC, sC, nullptr, 0, 0, tid);        // t2 -> sC[0:64]
    mm4<64, 32, 4, 4, 0>(sC, Wu2, sW, sC, nullptr, nullptr, 0, 0, tid);    // x1 -> sC[0:32]

    // decoder stage 1 (C=32): cat1 = [x1 | lat1] = sC[0:64]
    mm4<32, 32, 4, 4, 0>(sE1, Wl1, sW, sC + 32 * PITCH, nullptr, nullptr, 0, 0, tid);   // lat1
    mm4<64, 32, 4, 4, 1>(sC, Wm1, sW, sC, sC, nullptr, 0, 0, tid);         // t1 -> sC[0:32]

    // final upsample -> gmem [N, 32]
    mm4<32, 32, 4, 4, 2>(sC, Wu1, sW, nullptr, nullptr, out, row0, Ntot, tid);
}

extern "C" void kernel_launch(void* const* d_in, const int* in_sizes, int n_in,
                              void* d_out, int out_size)
{
    const float* feat = (const float*)d_in[0];
    // d_in[1] = coords (int32) — sparse structure only; unused for 1x1 subm convs
    const float* Win = (const float*)d_in[2];
    const float* We1 = (const float*)d_in[3];
    const float* We2 = (const float*)d_in[4];
    const float* We3 = (const float*)d_in[5];
    const float* Wl1 = (const float*)d_in[6];
    const float* Wl2 = (const float*)d_in[7];
    const float* Wl3 = (const float*)d_in[8];
    const float* Wm1 = (const float*)d_in[9];
    const float* Wm2 = (const float*)d_in[10];
    const float* Wm3 = (const float*)d_in[11];
    const float* Wu1 = (const float*)d_in[12];
    const float* Wu2 = (const float*)d_in[13];
    const float* Wu3 = (const float*)d_in[14];

    const int N = in_sizes[0] / 16;

    cudaFuncSetAttribute(fused_backbone_kernel,
                         cudaFuncAttributeMaxDynamicSharedMemorySize, SMEM_BYTES);

    const int grid = (N + RROWS - 1) / RROWS;
    fused_backbone_kernel<<<grid, THREADS, SMEM_BYTES>>>(
        feat, Win, We1, We2, We3, Wl1, Wl2, Wl3,
        Wm1, Wm2, Wm3, Wu1, Wu2, Wu3, (float*)d_out, N);
}

// round 8
// speedup vs baseline: 1.2612x; 1.0410x over previous
#include <cuda_runtime.h>

// Fused sparse-UNet backbone, round 8.
// Balanced 8x8 outer-product tiling (16 wavefronts vs 32 FFMA2 per warp-k =
// crossbar:fma 1:1, the SIMT floor) + R7's weight bank-conflict fixed by a
// swizzled weight staging layout: sW4[k][half][cg] = W4[k][2*cg+half], so both
// per-thread weight LDS.128s are lane-contiguous (conflict-free).

#define THREADS 256
#define RROWS   128
#define PITCH   132          // floats; 132*4=528 B, 16B-aligned rows
#define WBUF    8192         // weight staging buffer, floats (32 KB)

typedef unsigned long long ull;

__device__ __forceinline__ ull fma2(ull a, ull b, ull c) {
    ull d;
    asm("fma.rn.f32x2 %0, %1, %2, %3;" : "=l"(d) : "l"(a), "l"(b), "l"(c));
    return d;
}
__device__ __forceinline__ ull dup2(float x) {
    ull r;
    asm("mov.b64 %0, {%1, %1};" : "=l"(r) : "f"(x));
    return r;
}
__device__ __forceinline__ float2 unpk2(ull v) {
    float2 r;
    asm("mov.b64 {%0, %1}, %2;" : "=f"(r.x), "=f"(r.y) : "l"(v));
    return r;
}
__device__ __forceinline__ ull pk2(float2 v) {
    ull r;
    asm("mov.b64 %0, {%1, %2};" : "=l"(r) : "f"(v.x), "f"(v.y));
    return r;
}
__device__ __forceinline__ float frelu(float v) { return v > 0.f ? v : 0.f; }

// Thread grid: CG = COUT/CCG col-groups, RG = THREADS/CG row-groups.
// Thread: cg = tid % CG (cols [cg*CCG, +CCG)), rg = tid / CG (rows [rg*TRG, +TRG)).
// EPI: 0 relu->smem ; 1 relu+pairsum(redSrc)->smem ; 2 relu->gmem [N,COUT]
template<int CIN, int COUT, int TRG, int CCG, int EPI>
__device__ __forceinline__ void mm4(const float* __restrict__ sSrc,
                                    const float* __restrict__ Wg,
                                    float* __restrict__ sW,
                                    float* __restrict__ dst,
                                    const float* __restrict__ redSrc,
                                    float* __restrict__ gout,
                                    int row0, int Ntot, int tid)
{
    constexpr int CG    = COUT / CCG;
    constexpr int RG    = THREADS / CG;
    constexpr int PAIRS = TRG / 2;
    constexpr bool SWZ  = (CCG == 8);        // swizzled weight layout for 8-col threads
    static_assert(RG * TRG == RROWS, "row tiling");
    static_assert(TRG == 4 || TRG == 8, "TRG");
    static_assert(CCG == 4 || CCG == 8, "CCG");

    constexpr int KCC = (WBUF / COUT < CIN) ? (WBUF / COUT) : CIN;
    constexpr int NCH = CIN / KCC;
    constexpr int C4  = COUT / 4;            // float4s per k-row

    const int cg    = tid % CG;
    const int rg    = tid / CG;
    const int rbase = rg * TRG;
    const int cbase = cg * CCG;

    ull acc[PAIRS][CCG];
#pragma unroll
    for (int p = 0; p < PAIRS; p++)
#pragma unroll
        for (int j = 0; j < CCG; j++) acc[p][j] = 0ull;

    for (int ch = 0; ch < NCH; ch++) {
        __syncthreads();                              // sW free / prev stores visible
        {
            const float4* ws = (const float4*)(Wg + (size_t)ch * KCC * COUT);
            float4* wd = (float4*)sW;
            constexpr int WN = KCC * C4;
            for (int i = tid; i < WN; i += THREADS) {
                float4 v = ws[i];
                int d = i;
                if constexpr (SWZ) {
                    // dest[k][h][c] = src[k][2c+h] : both thread float4s contiguous
                    const int k = i / C4, r = i % C4;
                    d = k * C4 + ((r & 1) * (C4 / 2)) + (r >> 1);
                }
                wd[d] = v;
            }
        }
        __syncthreads();

        const float* sp = sSrc + (size_t)ch * KCC * PITCH + rbase;
#pragma unroll 4
        for (int k = 0; k < KCC; k++) {
            ull A[PAIRS];
            if constexpr (TRG == 8) {
                ulonglong2 a0 = *(const ulonglong2*)(sp + k * PITCH);
                ulonglong2 a1 = *(const ulonglong2*)(sp + k * PITCH + 4);
                A[0] = a0.x; A[1] = a0.y; A[2] = a1.x; A[3] = a1.y;
            } else {
                ulonglong2 a0 = *(const ulonglong2*)(sp + k * PITCH);
                A[0] = a0.x; A[1] = a0.y;
            }

            float w[CCG];
            if constexpr (CCG == 8) {
                const float4* wq = (const float4*)sW + k * C4 + cg;   // lane-contiguous
                float4 t0 = wq[0];
                float4 t1 = wq[C4 / 2];
                w[0] = t0.x; w[1] = t0.y; w[2] = t0.z; w[3] = t0.w;
                w[4] = t1.x; w[5] = t1.y; w[6] = t1.z; w[7] = t1.w;
            } else {
                float4 t0 = *(const float4*)(sW + k * COUT + cbase);  // lane-contiguous
                w[0] = t0.x; w[1] = t0.y; w[2] = t0.z; w[3] = t0.w;
            }
#pragma unroll
            for (int j = 0; j < CCG; j++) {
                ull wj = dup2(w[j]);
#pragma unroll
                for (int p = 0; p < PAIRS; p++)
                    acc[p][j] = fma2(A[p], wj, acc[p][j]);   // A*w + acc
            }
        }
    }

    // finalize in registers (redSrc reads BEFORE the sync)
#pragma unroll
    for (int j = 0; j < CCG; j++) {
        const int c = cbase + j;
#pragma unroll
        for (int p = 0; p < PAIRS; p++) {
            float2 v = unpk2(acc[p][j]);
            v.x = frelu(v.x); v.y = frelu(v.y);
            if (EPI == 1) {
                const int r0 = rbase + 2 * p;
                const float2 ra = *(const float2*)&redSrc[(2 * c) * PITCH + r0];
                const float2 rb = *(const float2*)&redSrc[(2 * c + 1) * PITCH + r0];
                v.x += ra.x + rb.x;
                v.y += ra.y + rb.y;
            }
            acc[p][j] = pk2(v);
        }
    }

    if (EPI == 2) {
        // final stage (CCG==4): row-major float4 stores to gmem
#pragma unroll
        for (int rr = 0; rr < TRG; rr++) {
            const int g = row0 + rbase + rr;
            if (g < Ntot) {
                float4 o;
                float2 v0 = unpk2(acc[rr / 2][0]);
                float2 v1 = unpk2(acc[rr / 2][1]);
                float2 v2 = unpk2(acc[rr / 2][2]);
                float2 v3 = unpk2(acc[rr / 2][3]);
                if (rr & 1) { o.x = v0.y; o.y = v1.y; o.z = v2.y; o.w = v3.y; }
                else        { o.x = v0.x; o.y = v1.x; o.z = v2.x; o.w = v3.x; }
                *(float4*)&gout[(size_t)g * COUT + cbase] = o;
            }
        }
        return;
    }

    __syncthreads();                                  // all reads of src done
#pragma unroll
    for (int j = 0; j < CCG; j++) {
        const int c = cbase + j;
#pragma unroll
        for (int p = 0; p < PAIRS; p++)
            *(float2*)&dst[c * PITCH + rbase + 2 * p] = unpk2(acc[p][j]);
    }
}

// smem: sE1 32ch, sE2 64ch, sC 256ch (PITCH floats/ch) + sW
#define SMEM_FLOATS ((32 + 64 + 256) * PITCH + WBUF)
#define SMEM_BYTES  (SMEM_FLOATS * 4)

__global__ void __launch_bounds__(THREADS, 1)
fused_backbone_kernel(const float* __restrict__ feat,
                      const float* __restrict__ Win,
                      const float* __restrict__ We1, const float* __restrict__ We2,
                      const float* __restrict__ We3,
                      const float* __restrict__ Wl1, const float* __restrict__ Wl2,
                      const float* __restrict__ Wl3,
                      const float* __restrict__ Wm1, const float* __restrict__ Wm2,
                      const float* __restrict__ Wm3,
                      const float* __restrict__ Wu1, const float* __restrict__ Wu2,
                      const float* __restrict__ Wu3,
                      float* __restrict__ out, int Ntot)
{
    extern __shared__ float smem[];
    float* sE1 = smem;                        // e1: 32 ch (persists)
    float* sE2 = sE1 + 32 * PITCH;            // e2: 64 ch (persists)
    float* sC  = sE2 + 64 * PITCH;            // workspace: 256 ch
    float* sW  = sC + 256 * PITCH;            // weight chunk buffer

    const int tid  = threadIdx.x;
    const int row0 = blockIdx.x * RROWS;

    // feat[row0 : row0+128, 0:16] -> sC[0:16] channel-major (coalesced reads)
    for (int idx = tid; idx < 16 * RROWS; idx += THREADS) {
        const int c = idx & 15, r = idx >> 4;
        const int gr = row0 + r;
        sC[c * PITCH + r] = (gr < Ntot) ? feat[(size_t)gr * 16 + c] : 0.f;
    }
    // mm4's leading __syncthreads covers the store->read hazard

    // encoder (src/dst may alias: epilogues are reg-deferred)
    mm4<16, 32, 4, 4, 0>(sC, Win, sW, sC, nullptr, nullptr, 0, 0, tid);    // x   -> sC[0:32]
    mm4<32, 32, 4, 4, 0>(sC, We1, sW, sE1, nullptr, nullptr, 0, 0, tid);   // e1  -> sE1
    mm4<32, 64, 8, 4, 0>(sE1, We2, sW, sE2, nullptr, nullptr, 0, 0, tid);  // e2  -> sE2
    mm4<64, 128, 8, 8, 0>(sE2, We3, sW, sC, nullptr, nullptr, 0, 0, tid);  // e3  -> sC[0:128]

    // decoder stage 3 (C=128): cat3 = [e3 | lat3] = sC[0:256]
    mm4<128, 128, 8, 8, 0>(sC, Wl3, sW, sC + 128 * PITCH, nullptr, nullptr, 0, 0, tid); // lat3
    mm4<256, 128, 8, 8, 1>(sC, Wm3, sW, sC, sC, nullptr, 0, 0, tid);       // t3 -> sC[0:128]
    mm4<128, 64, 8, 4, 0>(sC, Wu3, sW, sC, nullptr, nullptr, 0, 0, tid);   // x2 -> sC[0:64]

    // decoder stage 2 (C=64): cat2 = [x2 | lat2] = sC[0:128]
    mm4<64, 64, 8, 4, 0>(sE2, Wl2, sW, sC + 64 * PITCH, nullptr, nullptr, 0, 0, tid);   // lat2
    mm4<128, 64, 8, 4, 1>(sC, Wm2, sW, sC, sC, nullptr, 0, 0, tid);        // t2 -> sC[0:64]
    mm4<64, 32, 4, 4, 0>(sC, Wu2, sW, sC, nullptr, nullptr, 0, 0, tid);    // x1 -> sC[0:32]

    // decoder stage 1 (C=32): cat1 = [x1 | lat1] = sC[0:64]
    mm4<32, 32, 4, 4, 0>(sE1, Wl1, sW, sC + 32 * PITCH, nullptr, nullptr, 0, 0, tid);   // lat1
    mm4<64, 32, 4, 4, 1>(sC, Wm1, sW, sC, sC, nullptr, 0, 0, tid);         // t1 -> sC[0:32]

    // final upsample -> gmem [N, 32]
    mm4<32, 32, 4, 4, 2>(sC, Wu1, sW, nullptr, nullptr, out, row0, Ntot, tid);
}

extern "C" void kernel_launch(void* const* d_in, const int* in_sizes, int n_in,
                              void* d_out, int out_size)
{
    const float* feat = (const float*)d_in[0];
    // d_in[1] = coords (int32) — sparse structure only; unused for 1x1 subm convs
    const float* Win = (const float*)d_in[2];
    const float* We1 = (const float*)d_in[3];
    const float* We2 = (const float*)d_in[4];
    const float* We3 = (const float*)d_in[5];
    const float* Wl1 = (const float*)d_in[6];
    const float* Wl2 = (const float*)d_in[7];
    const float* Wl3 = (const float*)d_in[8];
    const float* Wm1 = (const float*)d_in[9];
    const float* Wm2 = (const float*)d_in[10];
    const float* Wm3 = (const float*)d_in[11];
    const float* Wu1 = (const float*)d_in[12];
    const float* Wu2 = (const float*)d_in[13];
    const float* Wu3 = (const float*)d_in[14];

    const int N = in_sizes[0] / 16;

    cudaFuncSetAttribute(fused_backbone_kernel,
                         cudaFuncAttributeMaxDynamicSharedMemorySize, SMEM_BYTES);

    const int grid = (N + RROWS - 1) / RROWS;
    fused_backbone_kernel<<<grid, THREADS, SMEM_BYTES>>>(
        feat, Win, We1, We2, We3, Wl1, Wl2, Wl3,
        Wm1, Wm2, Wm3, Wu1, Wu2, Wu3, (float*)d_out, N);
}

// round 10
// speedup vs baseline: 1.4771x; 1.1712x over previous
#include <cuda_runtime.h>
#include <cstdint>

// Fused sparse-UNet backbone, round 10: warp-level 3xTF32 via mma.sync
// (m16n8k8 HMMA — tcgen05 is unavailable: harness PTX target is base sm_103).
// 8 warps x 16 rows; per-warp-private activation scratch in SMEM; weights
// staged per-32k-chunk as tf32 hi/lo. D = Ahi*Bhi + Ahi*Blo + Alo*Bhi.

#define THREADS 256
#define MROWS   128
#define PW      260                    // scratch pitch (floats), ==4 mod 32
#define WSCR    (16 * PW)              // per-warp scratch floats
#define KC      32                     // k-chunk
#define PNMAX   (128 + 8)              // max weight pitch
#define OFF_WHI 0
#define OFF_WLO (KC * PNMAX)           // 4352
#define OFF_SCR (2 * KC * PNMAX)       // 8704
#define SMEM_FLOATS (OFF_SCR + 8 * WSCR)
#define SMEM_BYTES  (SMEM_FLOATS * 4)

__device__ __forceinline__ uint32_t tf32r(float x){
    uint32_t r; asm("cvt.rna.tf32.f32 %0, %1;" : "=r"(r) : "f"(x)); return r;
}
__device__ __forceinline__ float frelu(float v){ return v > 0.f ? v : 0.f; }

__device__ __forceinline__ void mma8(float* d, const uint32_t* a, const uint32_t* b){
    asm volatile("mma.sync.aligned.m16n8k8.row.col.f32.tf32.tf32.f32 "
        "{%0,%1,%2,%3},{%4,%5,%6,%7},{%8,%9},{%0,%1,%2,%3};"
        : "+f"(d[0]), "+f"(d[1]), "+f"(d[2]), "+f"(d[3])
        : "r"(a[0]), "r"(a[1]), "r"(a[2]), "r"(a[3]), "r"(b[0]), "r"(b[1]));
}

// One stage: out[16,N] (per warp) = relu(act[16,K] @ W[K,N]) (+ red for EPI=1).
// EPI: 0 -> scratch ; 1 -> merge (add pairsum of cat read from scratch) -> scratch ;
//      2 -> gmem [N rows,32]. ESAVE: keep a copy of outputs in eSave regs.
template<int K, int N, int EPI, bool ESAVE>
__device__ __forceinline__ void stage(const float* __restrict__ Wg,
                                      float* __restrict__ smem,
                                      float* __restrict__ scr,
                                      int aBase, int dBase,
                                      float* __restrict__ eSave,
                                      float* __restrict__ gout,
                                      int growBase, int Ntot, int tid)
{
    constexpr int PN  = N + 8;               // weight pitch, ==8 mod 32
    constexpr int NT  = N / 8;               // n-tiles per warp
    constexpr int KcC = (K < KC) ? K : KC;   // all K are 16 or multiples of 32
    constexpr int NCH = K / KcC;
    const int lane = tid & 31;
    const int qr = lane >> 2;                // 0..7
    const int qc = lane & 3;                 // 0..3

    float acc[NT][4];
#pragma unroll
    for (int j = 0; j < NT; j++){ acc[j][0]=acc[j][1]=acc[j][2]=acc[j][3]=0.f; }

    for (int ch = 0; ch < NCH; ch++){
        const int k0 = ch * KcC;
        __syncthreads();                     // all warps done with previous sW use
        {
            const float* wsrc = Wg + (size_t)k0 * N;
            for (int i = tid; i < KcC * N; i += THREADS){
                const int k = i / N, n = i % N;        // N is a power of two
                float w = wsrc[i];
                float hv = __uint_as_float(tf32r(w));
                smem[OFF_WHI + k * PN + n] = hv;
                smem[OFF_WLO + k * PN + n] = __uint_as_float(tf32r(w - hv));
            }
        }
        __syncthreads();

#pragma unroll
        for (int s = 0; s < KcC / 8; s++){
            const float* ap = scr + aBase + k0 + 8 * s;
            float a0 = ap[qr * PW + qc];
            float a1 = ap[(qr + 8) * PW + qc];
            float a2 = ap[qr * PW + qc + 4];
            float a3 = ap[(qr + 8) * PW + qc + 4];
            uint32_t ah[4] = { tf32r(a0), tf32r(a1), tf32r(a2), tf32r(a3) };
            uint32_t al[4] = { tf32r(a0 - __uint_as_float(ah[0])),
                               tf32r(a1 - __uint_as_float(ah[1])),
                               tf32r(a2 - __uint_as_float(ah[2])),
                               tf32r(a3 - __uint_as_float(ah[3])) };
            const float* bh = smem + OFF_WHI + (8 * s + qc) * PN + qr;
            const float* bl = smem + OFF_WLO + (8 * s + qc) * PN + qr;
#pragma unroll
            for (int j = 0; j < NT; j++){
                uint32_t bhi[2] = { __float_as_uint(bh[8 * j]),
                                    __float_as_uint(bh[4 * PN + 8 * j]) };
                uint32_t blo[2] = { __float_as_uint(bl[8 * j]),
                                    __float_as_uint(bl[4 * PN + 8 * j]) };
                mma8(acc[j], ah, bhi);
                mma8(acc[j], ah, blo);
                mma8(acc[j], al, bhi);
            }
        }
    }

    // epilogue. C frag: c0,c1 = row qr, cols 8j+2qc, +1 ; c2,c3 = row qr+8.
#pragma unroll
    for (int j = 0; j < NT; j++){
        float v0 = frelu(acc[j][0]), v1 = frelu(acc[j][1]);
        float v2 = frelu(acc[j][2]), v3 = frelu(acc[j][3]);
        if constexpr (EPI == 1){
            // red[col] = cat[2col]+cat[2col+1]; cols 8j+2qc(+1) -> cat 16j+4qc..+3
            const float4 qa = *(const float4*)&scr[qr * PW + aBase + 16 * j + 4 * qc];
            const float4 qb = *(const float4*)&scr[(qr + 8) * PW + aBase + 16 * j + 4 * qc];
            v0 += qa.x + qa.y;  v1 += qa.z + qa.w;
            v2 += qb.x + qb.y;  v3 += qb.z + qb.w;
        }
        if constexpr (ESAVE){
            eSave[4*j] = v0; eSave[4*j+1] = v1; eSave[4*j+2] = v2; eSave[4*j+3] = v3;
        }
        if constexpr (EPI == 2){
            const int g0 = growBase + qr;
            if (g0 < Ntot)
                *(float2*)&gout[(size_t)g0 * 32 + 8 * j + 2 * qc] = make_float2(v0, v1);
            if (g0 + 8 < Ntot)
                *(float2*)&gout[(size_t)(g0 + 8) * 32 + 8 * j + 2 * qc] = make_float2(v2, v3);
        } else {
            *(float2*)&scr[qr * PW + dBase + 8 * j + 2 * qc]       = make_float2(v0, v1);
            *(float2*)&scr[(qr + 8) * PW + dBase + 8 * j + 2 * qc] = make_float2(v2, v3);
        }
    }
}

// write saved e-regs (acc layout) back into scratch at channel base
template<int NT2>
__device__ __forceinline__ void restage(float* __restrict__ scr, int base,
                                        const float* __restrict__ e, int lane){
    const int qr = lane >> 2, qc = lane & 3;
#pragma unroll
    for (int j = 0; j < NT2; j++){
        *(float2*)&scr[qr * PW + base + 8 * j + 2 * qc]       = make_float2(e[4*j],   e[4*j+1]);
        *(float2*)&scr[(qr + 8) * PW + base + 8 * j + 2 * qc] = make_float2(e[4*j+2], e[4*j+3]);
    }
}

__global__ void __launch_bounds__(THREADS, 1)
backbone_mma(const float* __restrict__ feat,
             const float* __restrict__ Win,
             const float* __restrict__ We1, const float* __restrict__ We2,
             const float* __restrict__ We3,
             const float* __restrict__ Wl1, const float* __restrict__ Wl2,
             const float* __restrict__ Wl3,
             const float* __restrict__ Wm1, const float* __restrict__ Wm2,
             const float* __restrict__ Wm3,
             const float* __restrict__ Wu1, const float* __restrict__ Wu2,
             const float* __restrict__ Wu3,
             float* __restrict__ out, int Ntot)
{
    extern __shared__ float smem[];
    const int tid  = threadIdx.x;
    const int warp = tid >> 5, lane = tid & 31;
    float* scr = smem + OFF_SCR + warp * WSCR;    // this warp's 16-row scratch
    const int growBase = blockIdx.x * MROWS + warp * 16;

    // feat -> scratch ch 0..15 (each lane: one row-half, 2x float4)
    {
        const int r = lane >> 1, h = lane & 1;
        const int g = growBase + r;
        float4 f0 = make_float4(0,0,0,0), f1 = f0;
        if (g < Ntot){
            const float4* src = (const float4*)&feat[(size_t)g * 16 + h * 8];
            f0 = src[0]; f1 = src[1];
        }
        *(float4*)&scr[r * PW + h * 8]     = f0;
        *(float4*)&scr[r * PW + h * 8 + 4] = f1;
    }
    // (first stage's __syncthreads covers the store->read hazard)

    float e1r[16], e2r[32];

    // encoder
    stage<16,  32, 0, false>(Win, smem, scr, 0, 0,   nullptr, nullptr, 0, 0, tid);   // x  -> ch0-31
    stage<32,  32, 0, true >(We1, smem, scr, 0, 0,   e1r,     nullptr, 0, 0, tid);   // e1 -> ch0-31 + regs
    stage<32,  64, 0, true >(We2, smem, scr, 0, 0,   e2r,     nullptr, 0, 0, tid);   // e2 -> ch0-63 + regs
    stage<64, 128, 0, false>(We3, smem, scr, 0, 0,   nullptr, nullptr, 0, 0, tid);   // e3 -> ch0-127

    // decoder stage 3: cat3 = [e3 ch0-127 | lat3 ch128-255]
    stage<128,128, 0, false>(Wl3, smem, scr, 0, 128, nullptr, nullptr, 0, 0, tid);   // lat3
    stage<256,128, 1, false>(Wm3, smem, scr, 0, 0,   nullptr, nullptr, 0, 0, tid);   // t3 -> ch0-127
    stage<128, 64, 0, false>(Wu3, smem, scr, 0, 0,   nullptr, nullptr, 0, 0, tid);   // x2 -> ch0-63

    // decoder stage 2: cat2 = [x2 ch0-63 | lat2 ch64-127]
    restage<8>(scr, 64, e2r, lane);                                                  // e2 -> ch64-127
    stage<64,  64, 0, false>(Wl2, smem, scr, 64, 64, nullptr, nullptr, 0, 0, tid);   // lat2
    stage<128, 64, 1, false>(Wm2, smem, scr, 0, 0,   nullptr, nullptr, 0, 0, tid);   // t2 -> ch0-63
    stage<64,  32, 0, false>(Wu2, smem, scr, 0, 0,   nullptr, nullptr, 0, 0, tid);   // x1 -> ch0-31

    // decoder stage 1: cat1 = [x1 ch0-31 | lat1 ch32-63]
    restage<4>(scr, 32, e1r, lane);                                                  // e1 -> ch32-63
    stage<32,  32, 0, false>(Wl1, smem, scr, 32, 32, nullptr, nullptr, 0, 0, tid);   // lat1
    stage<64,  32, 1, false>(Wm1, smem, scr, 0, 0,   nullptr, nullptr, 0, 0, tid);   // t1 -> ch0-31

    // final upsample -> gmem [N, 32]
    stage<32,  32, 2, false>(Wu1, smem, scr, 0, 0,   nullptr, out, growBase, Ntot, tid);
}

extern "C" void kernel_launch(void* const* d_in, const int* in_sizes, int n_in,
                              void* d_out, int out_size)
{
    const float* feat = (const float*)d_in[0];
    // d_in[1] = coords — sparse structure only; unused for 1x1 subm convs
    const float* Win = (const float*)d_in[2];
    const float* We1 = (const float*)d_in[3];
    const float* We2 = (const float*)d_in[4];
    const float* We3 = (const float*)d_in[5];
    const float* Wl1 = (const float*)d_in[6];
    const float* Wl2 = (const float*)d_in[7];
    const float* Wl3 = (const float*)d_in[8];
    const float* Wm1 = (const float*)d_in[9];
    const float* Wm2 = (const float*)d_in[10];
    const float* Wm3 = (const float*)d_in[11];
    const float* Wu1 = (const float*)d_in[12];
    const float* Wu2 = (const float*)d_in[13];
    const float* Wu3 = (const float*)d_in[14];

    const int N = in_sizes[0] / 16;

    cudaFuncSetAttribute(backbone_mma,
                         cudaFuncAttributeMaxDynamicSharedMemorySize, SMEM_BYTES);

    const int grid = (N + MROWS - 1) / MROWS;
    backbone_mma<<<grid, THREADS, SMEM_BYTES>>>(
        feat, Win, We1, We2, We3, Wl1, Wl2, Wl3,
        Wm1, Wm2, Wm3, Wu1, Wu2, Wu3, (float*)d_out, N);
}